// round 16
// baseline (speedup 1.0000x reference)
#include <cuda_runtime.h>
#include <cuda_fp16.h>
#include <cstdint>
#include <math.h>

// ---------------- problem dims ----------------
#define Ldim 256
#define Bdim 64
#define Ddim 1024
#define Hdim 16
#define HDdim 64
#define Edim 8
#define Rdim 64
#define NTOK (Ldim*Bdim)          // 16384 tokens
#define SCALE_ADAPTER 0.1f
#define KEXT (4*Ddim + Edim*Rdim) // 4608 merged c_proj K

// ---------------- scratch (static device globals; allocation-free) ----------------
__device__ __half g_lnx  [NTOK*Ddim];
__device__ __half g_qkv  [NTOK*3*Ddim];
__device__ __half g_attn [NTOK*Ddim];
__device__ float  g_x1   [NTOK*Ddim];
__device__ __half g_x1h  [NTOK*Ddim];
__device__ __half g_ln2x [NTOK*Ddim];
__device__ __half g_h2e  [NTOK*KEXT];
__device__ __half g_inw  [3*Ddim*Ddim];
__device__ __half g_outw [Ddim*Ddim];
__device__ __half g_bigw [KEXT*Ddim];        // [cfc_w (4096 rows) | down_w (512 rows)], K=1024
__device__ __half g_cprw2[Ddim*KEXT];        // [c_proj_w | SCALE*up_w^T] merged
__device__ float  g_gates[Bdim*Edim];

// ---------------- helpers ----------------
__device__ __forceinline__ uint32_t smem_u32(const void* p) {
    uint32_t a;
    asm("{ .reg .u64 t; cvta.to.shared.u64 t, %1; cvt.u32.u64 %0, t; }" : "=r"(a) : "l"(p));
    return a;
}
__device__ __forceinline__ void ldsm_x4(uint32_t* r, uint32_t addr) {
    asm volatile("ldmatrix.sync.aligned.m8n8.x4.shared.b16 {%0,%1,%2,%3}, [%4];"
        : "=r"(r[0]), "=r"(r[1]), "=r"(r[2]), "=r"(r[3]) : "r"(addr));
}
__device__ __forceinline__ void ldsm_x4_t(uint32_t* r, uint32_t addr) {
    asm volatile("ldmatrix.sync.aligned.m8n8.x4.trans.shared.b16 {%0,%1,%2,%3}, [%4];"
        : "=r"(r[0]), "=r"(r[1]), "=r"(r[2]), "=r"(r[3]) : "r"(addr));
}
__device__ __forceinline__ void mma_f16(float* c, const uint32_t* a, uint32_t b0, uint32_t b1) {
    asm volatile("mma.sync.aligned.m16n8k16.row.col.f32.f16.f16.f32 "
        "{%0,%1,%2,%3}, {%4,%5,%6,%7}, {%8,%9}, {%0,%1,%2,%3};"
        : "+f"(c[0]), "+f"(c[1]), "+f"(c[2]), "+f"(c[3])
        : "r"(a[0]), "r"(a[1]), "r"(a[2]), "r"(a[3]), "r"(b0), "r"(b1));
}
__device__ __forceinline__ uint32_t ph2(float a, float b) {
    __half2 h = __floats2half2_rn(a, b);
    return *(uint32_t*)&h;
}
#define CP_ASYNC16(dst, src) \
    asm volatile("cp.async.cg.shared.global [%0], [%1], 16;" :: "r"(dst), "l"(src))
#define CP_COMMIT() asm volatile("cp.async.commit_group;" ::: "memory")

// ---------------- epilogues ----------------
struct EpiBias {
    const float* bias;
    __device__ __forceinline__ float operator()(float a, int m, int n) const {
        (void)m; return a + bias[n];
    }
};
struct EpiOutProj {
    const float* bias; const float* res; __half* x1h;
    __device__ __forceinline__ float operator()(float a, int m, int n) const {
        float v = a + bias[n] + res[(size_t)m*Ddim + n];
        x1h[(size_t)m*Ddim + n] = __float2half_rn(v);
        return v;
    }
};
struct EpiGeluAdapt {   // n<4096: QuickGELU(a+cfc_b); else gates*relu(a+down_b)
    const float* cfc_b; const float* down_b; const float* gates;
    __device__ __forceinline__ float operator()(float a, int m, int n) const {
        if (n < 4*Ddim) {
            float h = a + cfc_b[n];
            return h / (1.f + __expf(-1.702f * h));
        } else {
            const int nl = n - 4*Ddim;
            float h = fmaxf(a + down_b[nl], 0.f);
            return h * gates[(m & (Bdim-1))*Edim + (nl >> 6)];
        }
    }
};
struct EpiFinal2 {
    const float* bias; const float* x1;
    const float* gates; const float* up_b;
    __device__ __forceinline__ float operator()(float a, int m, int n) const {
        const int b = m & (Bdim-1);
        float gub = 0.f;
        #pragma unroll
        for (int e=0;e<Edim;e++) gub = fmaf(gates[b*Edim+e], up_b[e*Ddim+n], gub);
        return x1[(size_t)m*Ddim+n] + a + bias[n] + SCALE_ADAPTER * gub;
    }
};

template<class T> __device__ __forceinline__ void store_pair(T* C, size_t off, float x, float y);
template<> __device__ __forceinline__ void store_pair<float>(float* C, size_t off, float x, float y) {
    *(float2*)(C + off) = make_float2(x, y);
}
template<> __device__ __forceinline__ void store_pair<__half>(__half* C, size_t off, float x, float y) {
    *(__half2*)(C + off) = __floats2half2_rn(x, y);
}

// ---------------- fp16 mma.sync GEMM (3-stage, prefetch-first, one sync/iter) ----------------
// A selected per block column: nb < nsplit -> A1, else A2 (both [M,K] K-major).
#define BKg 64
#define LDH 72
#define STAGE_HALVES (128*LDH)
#define STAGE_BYTES (2*STAGE_HALVES*2)       // 36864
#define NST 3
#define TGM_SMEM (NST*STAGE_BYTES)           // 110592

template<class TOut, class Epi>
__global__ __launch_bounds__(256, 2)
void tgemm(const __half* __restrict__ A1, const __half* __restrict__ A2, int nsplit,
           const __half* __restrict__ Bw,
           TOut* __restrict__ C, int M, int N, int K, int ldc, Epi epi) {
    extern __shared__ __half hsm[];
    const int tid = threadIdx.x;
    const int wid = tid >> 5, lane = tid & 31;
    const int gid = lane >> 2, tig = lane & 3;
    const int wm = wid >> 2, wn = wid & 3;

    const int nb = blockIdx.x, mb = blockIdx.y;
    const __half* Ab = ((nb < nsplit) ? A1 : A2) + (size_t)mb*128*K;
    const __half* Bb = Bw + (size_t)nb*128*K;
    const int KT = K / BKg;

    const uint32_t smb = smem_u32(hsm);
    const int rowA = lane & 15, colA = (lane >> 4) * 8;
    const int rowB = ((lane >> 4) & 1) * 8 + (lane & 7), colB = ((lane >> 3) & 1) * 8;

    auto issue_stage = [&](int s) {
        const int buf = s % NST;
        const uint32_t base = smb + (uint32_t)buf * STAGE_BYTES;
        const __half* As = Ab + s*BKg;
        const __half* Bs = Bb + s*BKg;
        #pragma unroll
        for (int i=0;i<4;i++) {
            const int idx = tid + i*256;
            const int r = idx >> 3, c = idx & 7;
            const uint32_t dst = (uint32_t)(r*LDH*2 + c*16);
            CP_ASYNC16(base + dst, As + (size_t)r*K + c*8);
            CP_ASYNC16(base + STAGE_HALVES*2 + dst, Bs + (size_t)r*K + c*8);
        }
    };

    float acc[4][4][4];
    #pragma unroll
    for (int i=0;i<4;i++)
        #pragma unroll
        for (int j=0;j<4;j++)
            #pragma unroll
            for (int t=0;t<4;t++) acc[i][j][t] = 0.f;

    issue_stage(0); CP_COMMIT();
    if (KT > 1) issue_stage(1);
    CP_COMMIT();

    for (int kt=0; kt<KT; kt++) {
        asm volatile("cp.async.wait_group 1;" ::: "memory");  // stage kt landed
        __syncthreads();

        // prefetch FIRST: keeps 2 stages in flight during compute. Buffer
        // (kt+2)%3 == (kt-1)%3 is free: its readers (compute kt-1) are fenced
        // by the __syncthreads above.
        if (kt+2 < KT) issue_stage(kt+2);
        CP_COMMIT();   // exactly one group per iteration (possibly empty)

        const uint32_t baseA = smb + (uint32_t)(kt % NST) * STAGE_BYTES;
        const uint32_t baseB = baseA + STAGE_HALVES*2;

        #pragma unroll
        for (int ks=0; ks<4; ks++) {
            const int k0 = ks*16;
            uint32_t afr[4][4], bfr[2][4];
            #pragma unroll
            for (int mt=0; mt<4; mt++) {
                const int m0 = wm*64 + mt*16;
                ldsm_x4(afr[mt], baseA + (uint32_t)(((m0 + rowA)*LDH + k0 + colA) * 2));
            }
            #pragma unroll
            for (int p=0; p<2; p++) {
                const int n0 = wn*32 + p*16;
                ldsm_x4(bfr[p], baseB + (uint32_t)(((n0 + rowB)*LDH + k0 + colB) * 2));
            }
            #pragma unroll
            for (int mt=0; mt<4; mt++) {
                #pragma unroll
                for (int p=0; p<2; p++) {
                    mma_f16(acc[mt][2*p+0], afr[mt], bfr[p][0], bfr[p][1]);
                    mma_f16(acc[mt][2*p+1], afr[mt], bfr[p][2], bfr[p][3]);
                }
            }
        }
    }

    #pragma unroll
    for (int mt=0; mt<4; mt++) {
        const int m0 = mb*128 + wm*64 + mt*16 + gid;
        #pragma unroll
        for (int nt=0; nt<4; nt++) {
            const int n0 = nb*128 + wn*32 + nt*8 + tig*2;
            store_pair<TOut>(C, (size_t)m0*ldc + n0,
                epi(acc[mt][nt][0], m0, n0), epi(acc[mt][nt][1], m0, n0+1));
            store_pair<TOut>(C, (size_t)(m0+8)*ldc + n0,
                epi(acc[mt][nt][2], m0+8, n0), epi(acc[mt][nt][3], m0+8, n0+1));
        }
    }
}

// ---------------- tensor-core flash attention (no-max softmax) ----------------
#define ATT_LDH 72
#define ATT_SMEM (3*256*ATT_LDH*2)    // 110592

__global__ __launch_bounds__(256)
void attn_mma_kernel(const __half* __restrict__ qkv, __half* __restrict__ out) {
    extern __shared__ __half asmem[];
    __half* Qs = asmem;
    __half* Ks = asmem + 256*ATT_LDH;
    __half* Vs = asmem + 2*256*ATT_LDH;
    const int b = blockIdx.x >> 4;
    const int h = blockIdx.x & 15;
    const int tid = threadIdx.x, lane = tid & 31, wid = tid >> 5;
    const int gid = lane >> 2, tig = lane & 3;

    #pragma unroll
    for (int i = 0; i < 8; i++) {
        const int idx = tid + i*256;
        const int row = idx >> 3, c = idx & 7;
        const __half* src = qkv + ((size_t)row*Bdim + b)*(3*Ddim) + h*HDdim + c*8;
        *(uint4*)(Qs + row*ATT_LDH + c*8) = *(const uint4*)(src);
        *(uint4*)(Ks + row*ATT_LDH + c*8) = *(const uint4*)(src + Ddim);
        *(uint4*)(Vs + row*ATT_LDH + c*8) = *(const uint4*)(src + 2*Ddim);
    }
    __syncthreads();

    const uint32_t q_base = smem_u32(Qs);
    const uint32_t k_base = smem_u32(Ks);
    const uint32_t v_base = smem_u32(Vs);
    const int rowA = lane & 15, colA = (lane >> 4) * 8;
    const int rowB = ((lane >> 4) & 1) * 8 + (lane & 7), colB = ((lane >> 3) & 1) * 8;
    const int m0 = wid * 32;

    float oacc[2][8][4];
    #pragma unroll
    for (int i=0;i<2;i++)
        #pragma unroll
        for (int j=0;j<8;j++)
            #pragma unroll
            for (int t=0;t<4;t++) oacc[i][j][t] = 0.f;
    float lst[2][2] = {{0.f,0.f},{0.f,0.f}};

    #pragma unroll
    for (int c = 0; c < 4; c++) {
        const int kv0 = c*64;
        float sacc[2][8][4];
        #pragma unroll
        for (int i=0;i<2;i++)
            #pragma unroll
            for (int j=0;j<8;j++)
                #pragma unroll
                for (int t=0;t<4;t++) sacc[i][j][t] = 0.f;

        #pragma unroll
        for (int t = 0; t < 4; t++) {
            const int k0 = t*16;
            uint32_t aq[2][4];
            ldsm_x4(aq[0], q_base + (uint32_t)(((m0 +      rowA)*ATT_LDH + k0 + colA)*2));
            ldsm_x4(aq[1], q_base + (uint32_t)(((m0 + 16 + rowA)*ATT_LDH + k0 + colA)*2));
            #pragma unroll
            for (int j = 0; j < 4; j++) {
                uint32_t bk[4];
                ldsm_x4(bk, k_base + (uint32_t)(((kv0 + j*16 + rowB)*ATT_LDH + k0 + colB)*2));
                mma_f16(sacc[0][2*j],   aq[0], bk[0], bk[1]);
                mma_f16(sacc[0][2*j+1], aq[0], bk[2], bk[3]);
                mma_f16(sacc[1][2*j],   aq[1], bk[0], bk[1]);
                mma_f16(sacc[1][2*j+1], aq[1], bk[2], bk[3]);
            }
        }

        #pragma unroll
        for (int mt = 0; mt < 2; mt++) {
            #pragma unroll
            for (int r = 0; r < 2; r++) {
                float rs = 0.f;
                #pragma unroll
                for (int j = 0; j < 8; j++) {
                    const float p0 = __expf(sacc[mt][j][2*r]   * 0.125f);
                    const float p1 = __expf(sacc[mt][j][2*r+1] * 0.125f);
                    sacc[mt][j][2*r] = p0; sacc[mt][j][2*r+1] = p1;
                    rs += p0 + p1;
                }
                lst[mt][r] += rs;
            }
        }

        #pragma unroll
        for (int t = 0; t < 4; t++) {
            uint32_t ap[2][4];
            #pragma unroll
            for (int mt = 0; mt < 2; mt++) {
                ap[mt][0] = ph2(sacc[mt][2*t][0],   sacc[mt][2*t][1]);
                ap[mt][1] = ph2(sacc[mt][2*t][2],   sacc[mt][2*t][3]);
                ap[mt][2] = ph2(sacc[mt][2*t+1][0], sacc[mt][2*t+1][1]);
                ap[mt][3] = ph2(sacc[mt][2*t+1][2], sacc[mt][2*t+1][3]);
            }
            #pragma unroll
            for (int j = 0; j < 4; j++) {
                uint32_t bv[4];
                ldsm_x4_t(bv, v_base + (uint32_t)(((kv0 + t*16 + (lane & 15))*ATT_LDH + j*16 + (lane >> 4)*8)*2));
                mma_f16(oacc[0][2*j],   ap[0], bv[0], bv[1]);
                mma_f16(oacc[0][2*j+1], ap[0], bv[2], bv[3]);
                mma_f16(oacc[1][2*j],   ap[1], bv[0], bv[1]);
                mma_f16(oacc[1][2*j+1], ap[1], bv[2], bv[3]);
            }
        }
    }

    #pragma unroll
    for (int mt = 0; mt < 2; mt++) {
        #pragma unroll
        for (int r = 0; r < 2; r++) {
            float den = lst[mt][r];
            den += __shfl_xor_sync(0xffffffffu, den, 1);
            den += __shfl_xor_sync(0xffffffffu, den, 2);
            const float inv = 1.f / den;
            const int l_idx = m0 + mt*16 + gid + r*8;
            __half* dst = out + ((size_t)l_idx*Bdim + b)*Ddim + h*HDdim;
            #pragma unroll
            for (int j = 0; j < 8; j++)
                *(__half2*)(dst + j*8 + tig*2) =
                    __floats2half2_rn(oacc[mt][j][2*r]*inv, oacc[mt][j][2*r+1]*inv);
        }
    }
}

// ---------------- LayerNorm (half output) ----------------
__global__ __launch_bounds__(256) void ln_kernel(const float* __restrict__ x,
                                                 const float* __restrict__ w,
                                                 const float* __restrict__ b,
                                                 __half* __restrict__ out) {
    const int row = blockIdx.x;
    const int t = threadIdx.x;
    const float4 xv = ((const float4*)(x + (size_t)row*Ddim))[t];
    __shared__ float red[8];

    float s = xv.x + xv.y + xv.z + xv.w;
    #pragma unroll
    for (int o=16;o;o>>=1) s += __shfl_xor_sync(0xffffffffu, s, o);
    if ((t & 31) == 0) red[t>>5] = s;
    __syncthreads();
    float mean = 0.f;
    #pragma unroll
    for (int i=0;i<8;i++) mean += red[i];
    mean *= (1.f/Ddim);
    __syncthreads();

    const float d0=xv.x-mean, d1=xv.y-mean, d2=xv.z-mean, d3=xv.w-mean;
    float sq = d0*d0 + d1*d1 + d2*d2 + d3*d3;
    #pragma unroll
    for (int o=16;o;o>>=1) sq += __shfl_xor_sync(0xffffffffu, sq, o);
    if ((t & 31) == 0) red[t>>5] = sq;
    __syncthreads();
    float var = 0.f;
    #pragma unroll
    for (int i=0;i<8;i++) var += red[i];
    var *= (1.f/Ddim);
    const float rstd = rsqrtf(var + 1e-5f);

    const float4 wv = ((const float4*)w)[t];
    const float4 bv = ((const float4*)b)[t];
    __half2* o2 = (__half2*)(out + (size_t)row*Ddim);
    o2[2*t+0] = __floats2half2_rn(d0*rstd*wv.x + bv.x, d1*rstd*wv.y + bv.y);
    o2[2*t+1] = __floats2half2_rn(d2*rstd*wv.z + bv.z, d3*rstd*wv.w + bv.w);
}

// ---------------- gating ----------------
__global__ __launch_bounds__(256) void gate_logits_kernel(
        const float* __restrict__ x1, const float* __restrict__ w_gate,
        float* __restrict__ gates) {
    const int b = blockIdx.x;
    const int t = threadIdx.x;
    __shared__ float wred[8][Edim];

    const float4 xv = ((const float4*)(x1 + (size_t)b*Ddim))[t];
    float acc[Edim];
    #pragma unroll
    for (int e=0;e<Edim;e++) acc[e]=0.f;
    const float* wr = w_gate + (size_t)(4*t)*Edim;
    #pragma unroll
    for (int e=0;e<Edim;e++) acc[e] = fmaf(xv.x, wr[e],          acc[e]);
    #pragma unroll
    for (int e=0;e<Edim;e++) acc[e] = fmaf(xv.y, wr[Edim+e],     acc[e]);
    #pragma unroll
    for (int e=0;e<Edim;e++) acc[e] = fmaf(xv.z, wr[2*Edim+e],   acc[e]);
    #pragma unroll
    for (int e=0;e<Edim;e++) acc[e] = fmaf(xv.w, wr[3*Edim+e],   acc[e]);

    #pragma unroll
    for (int e=0;e<Edim;e++) {
        #pragma unroll
        for (int o=16;o;o>>=1) acc[e] += __shfl_xor_sync(0xffffffffu, acc[e], o);
    }
    if ((t & 31) == 0) {
        #pragma unroll
        for (int e=0;e<Edim;e++) wred[t>>5][e] = acc[e];
    }
    __syncthreads();

    if (t == 0) {
        float lg[Edim];
        #pragma unroll
        for (int e=0;e<Edim;e++) {
            float s = 0.f;
            #pragma unroll
            for (int w=0;w<8;w++) s += wred[w][e];
            lg[e] = s;
        }
        int i0=0; float v0=lg[0];
        #pragma unroll
        for (int e=1;e<Edim;e++) if (lg[e] > v0) { v0=lg[e]; i0=e; }
        int i1=-1; float v1=-3.4e38f;
        #pragma unroll
        for (int e=0;e<Edim;e++) if (e!=i0 && lg[e] > v1) { v1=lg[e]; i1=e; }
        const float ex  = __expf(v1 - v0);
        const float inv = 1.f/(1.f+ex);
        #pragma unroll
        for (int e=0;e<Edim;e++) gates[b*Edim+e] = 0.f;
        gates[b*Edim+i0] = inv;
        gates[b*Edim+i1] = ex*inv;
    }
}

__device__ __forceinline__ float cv_squared8(const float* t) {
    float mean = 0.f;
    #pragma unroll
    for (int e=0;e<Edim;e++) mean += t[e];
    mean *= (1.f/Edim);
    float var = 0.f;
    #pragma unroll
    for (int e=0;e<Edim;e++) { const float d = t[e]-mean; var += d*d; }
    var *= (1.f/(Edim-1));
    return var / (mean*mean + 1e-10f);
}

__global__ void gate_loss_kernel(const float* __restrict__ gates, float* __restrict__ loss_out) {
    __shared__ float sg[Bdim][Edim];
    const int b = threadIdx.x;
    #pragma unroll
    for (int e=0;e<Edim;e++) sg[b][e] = gates[b*Edim+e];
    __syncthreads();
    if (b == 0 && loss_out != nullptr) {
        float imp[Edim], ldc[Edim];
        #pragma unroll
        for (int e=0;e<Edim;e++) { imp[e]=0.f; ldc[e]=0.f; }
        for (int bb=0;bb<Bdim;bb++)
            #pragma unroll
            for (int e=0;e<Edim;e++) {
                const float g = sg[bb][e];
                imp[e] += g;
                if (g > 0.f) ldc[e] += 1.f;
            }
        loss_out[0] = 0.01f * (cv_squared8(imp) + cv_squared8(ldc));
    }
}

// ---------------- fused weight conversion (4 contiguous ranges) ----------------
#define R0 (3*Ddim*Ddim/4)           // in_w -> inw           : 786432
#define R1 (R0 + Ddim*Ddim/4)        // out_w -> outw         : +262144
#define R2 (R1 + 4*Ddim*Ddim/4)      // cfc_w -> bigw[0:4096] : +1048576
#define R3 (R2 + Edim*Rdim*Ddim/4)   // down_w -> bigw[4096:] : +131072

__global__ void convert_all_kernel(const float4* __restrict__ in_w,
                                   const float4* __restrict__ out_w,
                                   const float4* __restrict__ cfc_w,
                                   const float4* __restrict__ down_w,
                                   __half2* __restrict__ inw,
                                   __half2* __restrict__ outw,
                                   __half2* __restrict__ bigw) {
    const int i = blockIdx.x*blockDim.x + threadIdx.x;
    const float4* src; __half2* dst; int j;
    if (i < R0)       { src = in_w;   dst = inw;                   j = i; }
    else if (i < R1)  { src = out_w;  dst = outw;                  j = i - R0; }
    else if (i < R2)  { src = cfc_w;  dst = bigw;                  j = i - R1; }
    else if (i < R3)  { src = down_w; dst = bigw + 2*4*Ddim*Ddim/4; j = i - R2; }
    else return;
    const float4 v = src[j];
    dst[2*j+0] = __floats2half2_rn(v.x, v.y);
    dst[2*j+1] = __floats2half2_rn(v.z, v.w);
}

__global__ void f2h_cprw_kernel(const float* __restrict__ in, __half* __restrict__ out, int n4) {
    const int i = blockIdx.x*blockDim.x + threadIdx.x;
    if (i < n4) {
        const int n = i / (4*Ddim/4);
        const int c4 = i % (4*Ddim/4);
        const float4 v = ((const float4*)(in + (size_t)n*4*Ddim))[c4];
        __half2* dst = (__half2*)(out + (size_t)n*KEXT + c4*4);
        dst[0] = __floats2half2_rn(v.x, v.y);
        dst[1] = __floats2half2_rn(v.z, v.w);
    }
}
__global__ void transpose_up_kernel(const float* __restrict__ up_w, __half* __restrict__ out) {
    const int idx = blockIdx.x*blockDim.x + threadIdx.x;
    const int total = Ddim*Edim*Rdim/4;
    if (idx < total) {
        const int r4 = idx % (Rdim/4);
        const int de = idx / (Rdim/4);
        const int e = de % Edim;
        const int d = de / Edim;
        const float4 v = ((const float4*)(up_w + (size_t)e*Ddim*Rdim + (size_t)d*Rdim))[r4];
        __half2* dst = (__half2*)(out + (size_t)d*KEXT + 4*Ddim + e*Rdim + r4*4);
        dst[0] = __floats2half2_rn(SCALE_ADAPTER*v.x, SCALE_ADAPTER*v.y);
        dst[1] = __floats2half2_rn(SCALE_ADAPTER*v.z, SCALE_ADAPTER*v.w);
    }
}

// ---------------- launch ----------------
extern "C" void kernel_launch(void* const* d_in, const int* in_sizes, int n_in,
                              void* d_out, int out_size) {
    (void)in_sizes; (void)n_in;
    const float* x       = (const float*)d_in[0];
    const float* ln1_w   = (const float*)d_in[1];
    const float* ln1_b   = (const float*)d_in[2];
    const float* in_w    = (const float*)d_in[3];
    const float* in_b    = (const float*)d_in[4];
    const float* out_w   = (const float*)d_in[5];
    const float* out_b   = (const float*)d_in[6];
    const float* ln2_w   = (const float*)d_in[7];
    const float* ln2_b   = (const float*)d_in[8];
    const float* cfc_w   = (const float*)d_in[9];
    const float* cfc_b   = (const float*)d_in[10];
    const float* cproj_w = (const float*)d_in[11];
    const float* cproj_b = (const float*)d_in[12];
    const float* w_gate  = (const float*)d_in[13];
    const float* down_w  = (const float*)d_in[14];
    const float* down_b  = (const float*)d_in[15];
    const float* up_w    = (const float*)d_in[16];
    const float* up_b    = (const float*)d_in[17];
    float* out = (float*)d_out;

    void* p;
    cudaGetSymbolAddress(&p, g_lnx);   __half* lnx  = (__half*)p;
    cudaGetSymbolAddress(&p, g_qkv);   __half* qkv  = (__half*)p;
    cudaGetSymbolAddress(&p, g_attn);  __half* attn = (__half*)p;
    cudaGetSymbolAddress(&p, g_x1);    float*  x1   = (float*)p;
    cudaGetSymbolAddress(&p, g_x1h);   __half* x1h  = (__half*)p;
    cudaGetSymbolAddress(&p, g_ln2x);  __half* ln2x = (__half*)p;
    cudaGetSymbolAddress(&p, g_h2e);   __half* h2e  = (__half*)p;
    cudaGetSymbolAddress(&p, g_inw);   __half* inw  = (__half*)p;
    cudaGetSymbolAddress(&p, g_outw);  __half* outw = (__half*)p;
    cudaGetSymbolAddress(&p, g_bigw);  __half* bigw = (__half*)p;
    cudaGetSymbolAddress(&p, g_cprw2); __half* cprw2= (__half*)p;
    cudaGetSymbolAddress(&p, g_gates); float*  gates= (float*)p;

    cudaFuncSetAttribute(attn_mma_kernel, cudaFuncAttributeMaxDynamicSharedMemorySize, ATT_SMEM);
    cudaFuncSetAttribute((tgemm<__half, EpiBias>),      cudaFuncAttributeMaxDynamicSharedMemorySize, TGM_SMEM);
    cudaFuncSetAttribute((tgemm<float,  EpiOutProj>),   cudaFuncAttributeMaxDynamicSharedMemorySize, TGM_SMEM);
    cudaFuncSetAttribute((tgemm<__half, EpiGeluAdapt>), cudaFuncAttributeMaxDynamicSharedMemorySize, TGM_SMEM);
    cudaFuncSetAttribute((tgemm<float,  EpiFinal2>),    cudaFuncAttributeMaxDynamicSharedMemorySize, TGM_SMEM);

    float* loss_ptr = (out_size > NTOK*Ddim) ? (out + NTOK*Ddim) : nullptr;

    // 0) weight conversion fp32 -> fp16 (fused)
    convert_all_kernel<<<(R3+255)/256, 256>>>(
        (const float4*)in_w, (const float4*)out_w, (const float4*)cfc_w, (const float4*)down_w,
        (__half2*)inw, (__half2*)outw, (__half2*)bigw);
    f2h_cprw_kernel<<<(Ddim*Ddim+255)/256, 256>>>(cproj_w, cprw2, Ddim*Ddim);
    transpose_up_kernel<<<(Ddim*Edim*Rdim/4 + 255)/256, 256>>>(up_w, cprw2);

    // 1) LN1 (half)
    ln_kernel<<<NTOK, 256>>>(x, ln1_w, ln1_b, lnx);
    // 2) QKV projection (+bias) -> half
    tgemm<<<dim3(3*Ddim/128, NTOK/128), 256, TGM_SMEM>>>(lnx, lnx, 1<<30, inw, qkv,
        NTOK, 3*Ddim, Ddim, 3*Ddim, EpiBias{in_b});
    // 3) attention (tensor-core flash, no-max softmax) -> half
    attn_mma_kernel<<<Bdim*Hdim, 256, ATT_SMEM>>>(qkv, attn);
    // 4) out-proj (+bias, +x residual) -> x1 (fp32) and x1h (half)
    tgemm<<<dim3(Ddim/128, NTOK/128), 256, TGM_SMEM>>>(attn, attn, 1<<30, outw, x1,
        NTOK, Ddim, Ddim, Ddim, EpiOutProj{out_b, x, x1h});
    // 5) gating (parallel) + moe_loss
    gate_logits_kernel<<<Bdim, 256>>>(x1, w_gate, gates);
    gate_loss_kernel<<<1, Bdim>>>(gates, loss_ptr);
    // 6) LN2 (half)
    ln_kernel<<<NTOK, 256>>>(x1, ln2_w, ln2_b, ln2x);
    // 7+8) merged c_fc (A=ln2x, n<4096) + adapter down (A=x1h, n>=4096) -> h2e
    tgemm<<<dim3(KEXT/128, NTOK/128), 256, TGM_SMEM>>>(ln2x, x1h, 4*Ddim/128, bigw, h2e,
        NTOK, KEXT, Ddim, KEXT, EpiGeluAdapt{cfc_b, down_b, gates});
    // 9) merged c_proj + adapter up
    tgemm<<<dim3(Ddim/128, NTOK/128), 256, TGM_SMEM>>>(h2e, h2e, 1<<30, cprw2, out,
        NTOK, Ddim, KEXT, Ddim, EpiFinal2{cproj_b, x1, gates, up_b});
}

// round 17
// speedup vs baseline: 1.0585x; 1.0585x over previous
#include <cuda_runtime.h>
#include <cuda_fp16.h>
#include <cstdint>
#include <math.h>

// ---------------- problem dims ----------------
#define Ldim 256
#define Bdim 64
#define Ddim 1024
#define Hdim 16
#define HDdim 64
#define Edim 8
#define Rdim 64
#define NTOK (Ldim*Bdim)          // 16384 tokens
#define SCALE_ADAPTER 0.1f
#define KEXT (4*Ddim + Edim*Rdim) // 4608 merged c_proj K

// ---------------- scratch (static device globals; allocation-free) ----------------
__device__ __half g_lnx  [NTOK*Ddim];
__device__ __half g_qkv  [NTOK*3*Ddim];
__device__ __half g_attn [NTOK*Ddim];
__device__ float  g_x1   [NTOK*Ddim];
__device__ __half g_x1h  [NTOK*Ddim];
__device__ __half g_ln2x [NTOK*Ddim];
__device__ __half g_h2e  [NTOK*KEXT];
__device__ __half g_inw  [3*Ddim*Ddim];
__device__ __half g_outw [Ddim*Ddim];
__device__ __half g_bigw [KEXT*Ddim];        // [cfc_w (4096 rows) | down_w (512 rows)], K=1024
__device__ __half g_cprw2[Ddim*KEXT];        // [c_proj_w | SCALE*up_w^T] merged
__device__ float  g_gates[Bdim*Edim];

// ---------------- helpers ----------------
__device__ __forceinline__ uint32_t smem_u32(const void* p) {
    uint32_t a;
    asm("{ .reg .u64 t; cvta.to.shared.u64 t, %1; cvt.u32.u64 %0, t; }" : "=r"(a) : "l"(p));
    return a;
}
__device__ __forceinline__ void ldsm_x4(uint32_t* r, uint32_t addr) {
    asm volatile("ldmatrix.sync.aligned.m8n8.x4.shared.b16 {%0,%1,%2,%3}, [%4];"
        : "=r"(r[0]), "=r"(r[1]), "=r"(r[2]), "=r"(r[3]) : "r"(addr));
}
__device__ __forceinline__ void ldsm_x4_t(uint32_t* r, uint32_t addr) {
    asm volatile("ldmatrix.sync.aligned.m8n8.x4.trans.shared.b16 {%0,%1,%2,%3}, [%4];"
        : "=r"(r[0]), "=r"(r[1]), "=r"(r[2]), "=r"(r[3]) : "r"(addr));
}
__device__ __forceinline__ void mma_f16(float* c, const uint32_t* a, uint32_t b0, uint32_t b1) {
    asm volatile("mma.sync.aligned.m16n8k16.row.col.f32.f16.f16.f32 "
        "{%0,%1,%2,%3}, {%4,%5,%6,%7}, {%8,%9}, {%0,%1,%2,%3};"
        : "+f"(c[0]), "+f"(c[1]), "+f"(c[2]), "+f"(c[3])
        : "r"(a[0]), "r"(a[1]), "r"(a[2]), "r"(a[3]), "r"(b0), "r"(b1));
}
__device__ __forceinline__ uint32_t ph2(float a, float b) {
    __half2 h = __floats2half2_rn(a, b);
    return *(uint32_t*)&h;
}
#define CP_ASYNC16(dst, src) \
    asm volatile("cp.async.cg.shared.global [%0], [%1], 16;" :: "r"(dst), "l"(src))
#define CP_COMMIT() asm volatile("cp.async.commit_group;" ::: "memory")

// ---------------- epilogues ----------------
struct EpiBias {
    const float* bias;
    __device__ __forceinline__ float operator()(float a, int m, int n) const {
        (void)m; return a + bias[n];
    }
};
struct EpiOutProj {
    const float* bias; const float* res; __half* x1h;
    __device__ __forceinline__ float operator()(float a, int m, int n) const {
        float v = a + bias[n] + res[(size_t)m*Ddim + n];
        x1h[(size_t)m*Ddim + n] = __float2half_rn(v);
        return v;
    }
};
struct EpiGeluAdapt {   // n<4096: QuickGELU(a+cfc_b); else gates*relu(a+down_b)
    const float* cfc_b; const float* down_b; const float* gates;
    __device__ __forceinline__ float operator()(float a, int m, int n) const {
        if (n < 4*Ddim) {
            float h = a + cfc_b[n];
            return h / (1.f + __expf(-1.702f * h));
        } else {
            const int nl = n - 4*Ddim;
            float h = fmaxf(a + down_b[nl], 0.f);
            return h * gates[(m & (Bdim-1))*Edim + (nl >> 6)];
        }
    }
};
struct EpiFinal2 {
    const float* bias; const float* x1;
    const float* gates; const float* up_b;
    __device__ __forceinline__ float operator()(float a, int m, int n) const {
        const int b = m & (Bdim-1);
        float gub = 0.f;
        #pragma unroll
        for (int e=0;e<Edim;e++) gub = fmaf(gates[b*Edim+e], up_b[e*Ddim+n], gub);
        return x1[(size_t)m*Ddim+n] + a + bias[n] + SCALE_ADAPTER * gub;
    }
};

template<class T> __device__ __forceinline__ void store_pair(T* C, size_t off, float x, float y);
template<> __device__ __forceinline__ void store_pair<float>(float* C, size_t off, float x, float y) {
    *(float2*)(C + off) = make_float2(x, y);
}
template<> __device__ __forceinline__ void store_pair<__half>(__half* C, size_t off, float x, float y) {
    *(__half2*)(C + off) = __floats2half2_rn(x, y);
}

// ---------------- fp16 mma.sync GEMM (3-stage, compute-then-issue, one sync/iter) ----------------
// A selected per block column: nb < nsplit -> A1, else A2 (both [M,K] K-major).
#define BKg 64
#define LDH 72
#define STAGE_HALVES (128*LDH)
#define STAGE_BYTES (2*STAGE_HALVES*2)       // 36864
#define NST 3
#define TGM_SMEM (NST*STAGE_BYTES)           // 110592

template<class TOut, class Epi>
__global__ __launch_bounds__(256, 2)
void tgemm(const __half* __restrict__ A1, const __half* __restrict__ A2, int nsplit,
           const __half* __restrict__ Bw,
           TOut* __restrict__ C, int M, int N, int K, int ldc, Epi epi) {
    extern __shared__ __half hsm[];
    const int tid = threadIdx.x;
    const int wid = tid >> 5, lane = tid & 31;
    const int gid = lane >> 2, tig = lane & 3;
    const int wm = wid >> 2, wn = wid & 3;

    const int nb = blockIdx.x, mb = blockIdx.y;
    const __half* Ab = ((nb < nsplit) ? A1 : A2) + (size_t)mb*128*K;
    const __half* Bb = Bw + (size_t)nb*128*K;
    const int KT = K / BKg;

    const uint32_t smb = smem_u32(hsm);
    const int rowA = lane & 15, colA = (lane >> 4) * 8;
    const int rowB = ((lane >> 4) & 1) * 8 + (lane & 7), colB = ((lane >> 3) & 1) * 8;

    auto issue_stage = [&](int s) {
        const int buf = s % NST;
        const uint32_t base = smb + (uint32_t)buf * STAGE_BYTES;
        const __half* As = Ab + s*BKg;
        const __half* Bs = Bb + s*BKg;
        #pragma unroll
        for (int i=0;i<4;i++) {
            const int idx = tid + i*256;
            const int r = idx >> 3, c = idx & 7;
            const uint32_t dst = (uint32_t)(r*LDH*2 + c*16);
            CP_ASYNC16(base + dst, As + (size_t)r*K + c*8);
            CP_ASYNC16(base + STAGE_HALVES*2 + dst, Bs + (size_t)r*K + c*8);
        }
    };

    float acc[4][4][4];
    #pragma unroll
    for (int i=0;i<4;i++)
        #pragma unroll
        for (int j=0;j<4;j++)
            #pragma unroll
            for (int t=0;t<4;t++) acc[i][j][t] = 0.f;

    issue_stage(0); CP_COMMIT();
    if (KT > 1) issue_stage(1);
    CP_COMMIT();

    for (int kt=0; kt<KT; kt++) {
        asm volatile("cp.async.wait_group 1;" ::: "memory");  // stage kt landed
        __syncthreads();

        const uint32_t baseA = smb + (uint32_t)(kt % NST) * STAGE_BYTES;
        const uint32_t baseB = baseA + STAGE_HALVES*2;

        #pragma unroll
        for (int ks=0; ks<4; ks++) {
            const int k0 = ks*16;
            uint32_t afr[4][4], bfr[2][4];
            #pragma unroll
            for (int mt=0; mt<4; mt++) {
                const int m0 = wm*64 + mt*16;
                ldsm_x4(afr[mt], baseA + (uint32_t)(((m0 + rowA)*LDH + k0 + colA) * 2));
            }
            #pragma unroll
            for (int p=0; p<2; p++) {
                const int n0 = wn*32 + p*16;
                ldsm_x4(bfr[p], baseB + (uint32_t)(((n0 + rowB)*LDH + k0 + colB) * 2));
            }
            #pragma unroll
            for (int mt=0; mt<4; mt++) {
                #pragma unroll
                for (int p=0; p<2; p++) {
                    mma_f16(acc[mt][2*p+0], afr[mt], bfr[p][0], bfr[p][1]);
                    mma_f16(acc[mt][2*p+1], afr[mt], bfr[p][2], bfr[p][3]);
                }
            }
        }

        // issue AFTER compute (R14 order): the cp.async burst overlaps the
        // MMA-saturated tail instead of delaying the first ldsm of this iter.
        if (kt+2 < KT) issue_stage(kt+2);
        CP_COMMIT();
    }

    #pragma unroll
    for (int mt=0; mt<4; mt++) {
        const int m0 = mb*128 + wm*64 + mt*16 + gid;
        #pragma unroll
        for (int nt=0; nt<4; nt++) {
            const int n0 = nb*128 + wn*32 + nt*8 + tig*2;
            store_pair<TOut>(C, (size_t)m0*ldc + n0,
                epi(acc[mt][nt][0], m0, n0), epi(acc[mt][nt][1], m0, n0+1));
            store_pair<TOut>(C, (size_t)(m0+8)*ldc + n0,
                epi(acc[mt][nt][2], m0+8, n0), epi(acc[mt][nt][3], m0+8, n0+1));
        }
    }
}

// ---------------- tensor-core flash attention (no-max softmax) ----------------
#define ATT_LDH 72
#define ATT_SMEM (3*256*ATT_LDH*2)    // 110592

__global__ __launch_bounds__(256)
void attn_mma_kernel(const __half* __restrict__ qkv, __half* __restrict__ out) {
    extern __shared__ __half asmem[];
    __half* Qs = asmem;
    __half* Ks = asmem + 256*ATT_LDH;
    __half* Vs = asmem + 2*256*ATT_LDH;
    const int b = blockIdx.x >> 4;
    const int h = blockIdx.x & 15;
    const int tid = threadIdx.x, lane = tid & 31, wid = tid >> 5;
    const int gid = lane >> 2, tig = lane & 3;

    #pragma unroll
    for (int i = 0; i < 8; i++) {
        const int idx = tid + i*256;
        const int row = idx >> 3, c = idx & 7;
        const __half* src = qkv + ((size_t)row*Bdim + b)*(3*Ddim) + h*HDdim + c*8;
        *(uint4*)(Qs + row*ATT_LDH + c*8) = *(const uint4*)(src);
        *(uint4*)(Ks + row*ATT_LDH + c*8) = *(const uint4*)(src + Ddim);
        *(uint4*)(Vs + row*ATT_LDH + c*8) = *(const uint4*)(src + 2*Ddim);
    }
    __syncthreads();

    const uint32_t q_base = smem_u32(Qs);
    const uint32_t k_base = smem_u32(Ks);
    const uint32_t v_base = smem_u32(Vs);
    const int rowA = lane & 15, colA = (lane >> 4) * 8;
    const int rowB = ((lane >> 4) & 1) * 8 + (lane & 7), colB = ((lane >> 3) & 1) * 8;
    const int m0 = wid * 32;

    float oacc[2][8][4];
    #pragma unroll
    for (int i=0;i<2;i++)
        #pragma unroll
        for (int j=0;j<8;j++)
            #pragma unroll
            for (int t=0;t<4;t++) oacc[i][j][t] = 0.f;
    float lst[2][2] = {{0.f,0.f},{0.f,0.f}};

    #pragma unroll
    for (int c = 0; c < 4; c++) {
        const int kv0 = c*64;
        float sacc[2][8][4];
        #pragma unroll
        for (int i=0;i<2;i++)
            #pragma unroll
            for (int j=0;j<8;j++)
                #pragma unroll
                for (int t=0;t<4;t++) sacc[i][j][t] = 0.f;

        #pragma unroll
        for (int t = 0; t < 4; t++) {
            const int k0 = t*16;
            uint32_t aq[2][4];
            ldsm_x4(aq[0], q_base + (uint32_t)(((m0 +      rowA)*ATT_LDH + k0 + colA)*2));
            ldsm_x4(aq[1], q_base + (uint32_t)(((m0 + 16 + rowA)*ATT_LDH + k0 + colA)*2));
            #pragma unroll
            for (int j = 0; j < 4; j++) {
                uint32_t bk[4];
                ldsm_x4(bk, k_base + (uint32_t)(((kv0 + j*16 + rowB)*ATT_LDH + k0 + colB)*2));
                mma_f16(sacc[0][2*j],   aq[0], bk[0], bk[1]);
                mma_f16(sacc[0][2*j+1], aq[0], bk[2], bk[3]);
                mma_f16(sacc[1][2*j],   aq[1], bk[0], bk[1]);
                mma_f16(sacc[1][2*j+1], aq[1], bk[2], bk[3]);
            }
        }

        #pragma unroll
        for (int mt = 0; mt < 2; mt++) {
            #pragma unroll
            for (int r = 0; r < 2; r++) {
                float rs = 0.f;
                #pragma unroll
                for (int j = 0; j < 8; j++) {
                    const float p0 = __expf(sacc[mt][j][2*r]   * 0.125f);
                    const float p1 = __expf(sacc[mt][j][2*r+1] * 0.125f);
                    sacc[mt][j][2*r] = p0; sacc[mt][j][2*r+1] = p1;
                    rs += p0 + p1;
                }
                lst[mt][r] += rs;
            }
        }

        #pragma unroll
        for (int t = 0; t < 4; t++) {
            uint32_t ap[2][4];
            #pragma unroll
            for (int mt = 0; mt < 2; mt++) {
                ap[mt][0] = ph2(sacc[mt][2*t][0],   sacc[mt][2*t][1]);
                ap[mt][1] = ph2(sacc[mt][2*t][2],   sacc[mt][2*t][3]);
                ap[mt][2] = ph2(sacc[mt][2*t+1][0], sacc[mt][2*t+1][1]);
                ap[mt][3] = ph2(sacc[mt][2*t+1][2], sacc[mt][2*t+1][3]);
            }
            #pragma unroll
            for (int j = 0; j < 4; j++) {
                uint32_t bv[4];
                ldsm_x4_t(bv, v_base + (uint32_t)(((kv0 + t*16 + (lane & 15))*ATT_LDH + j*16 + (lane >> 4)*8)*2));
                mma_f16(oacc[0][2*j],   ap[0], bv[0], bv[1]);
                mma_f16(oacc[0][2*j+1], ap[0], bv[2], bv[3]);
                mma_f16(oacc[1][2*j],   ap[1], bv[0], bv[1]);
                mma_f16(oacc[1][2*j+1], ap[1], bv[2], bv[3]);
            }
        }
    }

    #pragma unroll
    for (int mt = 0; mt < 2; mt++) {
        #pragma unroll
        for (int r = 0; r < 2; r++) {
            float den = lst[mt][r];
            den += __shfl_xor_sync(0xffffffffu, den, 1);
            den += __shfl_xor_sync(0xffffffffu, den, 2);
            const float inv = 1.f / den;
            const int l_idx = m0 + mt*16 + gid + r*8;
            __half* dst = out + ((size_t)l_idx*Bdim + b)*Ddim + h*HDdim;
            #pragma unroll
            for (int j = 0; j < 8; j++)
                *(__half2*)(dst + j*8 + tig*2) =
                    __floats2half2_rn(oacc[mt][j][2*r]*inv, oacc[mt][j][2*r+1]*inv);
        }
    }
}

// ---------------- LayerNorm (half output) ----------------
__global__ __launch_bounds__(256) void ln_kernel(const float* __restrict__ x,
                                                 const float* __restrict__ w,
                                                 const float* __restrict__ b,
                                                 __half* __restrict__ out) {
    const int row = blockIdx.x;
    const int t = threadIdx.x;
    const float4 xv = ((const float4*)(x + (size_t)row*Ddim))[t];
    __shared__ float red[8];

    float s = xv.x + xv.y + xv.z + xv.w;
    #pragma unroll
    for (int o=16;o;o>>=1) s += __shfl_xor_sync(0xffffffffu, s, o);
    if ((t & 31) == 0) red[t>>5] = s;
    __syncthreads();
    float mean = 0.f;
    #pragma unroll
    for (int i=0;i<8;i++) mean += red[i];
    mean *= (1.f/Ddim);
    __syncthreads();

    const float d0=xv.x-mean, d1=xv.y-mean, d2=xv.z-mean, d3=xv.w-mean;
    float sq = d0*d0 + d1*d1 + d2*d2 + d3*d3;
    #pragma unroll
    for (int o=16;o;o>>=1) sq += __shfl_xor_sync(0xffffffffu, sq, o);
    if ((t & 31) == 0) red[t>>5] = sq;
    __syncthreads();
    float var = 0.f;
    #pragma unroll
    for (int i=0;i<8;i++) var += red[i];
    var *= (1.f/Ddim);
    const float rstd = rsqrtf(var + 1e-5f);

    const float4 wv = ((const float4*)w)[t];
    const float4 bv = ((const float4*)b)[t];
    __half2* o2 = (__half2*)(out + (size_t)row*Ddim);
    o2[2*t+0] = __floats2half2_rn(d0*rstd*wv.x + bv.x, d1*rstd*wv.y + bv.y);
    o2[2*t+1] = __floats2half2_rn(d2*rstd*wv.z + bv.z, d3*rstd*wv.w + bv.w);
}

// ---------------- gating ----------------
__global__ __launch_bounds__(256) void gate_logits_kernel(
        const float* __restrict__ x1, const float* __restrict__ w_gate,
        float* __restrict__ gates) {
    const int b = blockIdx.x;
    const int t = threadIdx.x;
    __shared__ float wred[8][Edim];

    const float4 xv = ((const float4*)(x1 + (size_t)b*Ddim))[t];
    float acc[Edim];
    #pragma unroll
    for (int e=0;e<Edim;e++) acc[e]=0.f;
    const float* wr = w_gate + (size_t)(4*t)*Edim;
    #pragma unroll
    for (int e=0;e<Edim;e++) acc[e] = fmaf(xv.x, wr[e],          acc[e]);
    #pragma unroll
    for (int e=0;e<Edim;e++) acc[e] = fmaf(xv.y, wr[Edim+e],     acc[e]);
    #pragma unroll
    for (int e=0;e<Edim;e++) acc[e] = fmaf(xv.z, wr[2*Edim+e],   acc[e]);
    #pragma unroll
    for (int e=0;e<Edim;e++) acc[e] = fmaf(xv.w, wr[3*Edim+e],   acc[e]);

    #pragma unroll
    for (int e=0;e<Edim;e++) {
        #pragma unroll
        for (int o=16;o;o>>=1) acc[e] += __shfl_xor_sync(0xffffffffu, acc[e], o);
    }
    if ((t & 31) == 0) {
        #pragma unroll
        for (int e=0;e<Edim;e++) wred[t>>5][e] = acc[e];
    }
    __syncthreads();

    if (t == 0) {
        float lg[Edim];
        #pragma unroll
        for (int e=0;e<Edim;e++) {
            float s = 0.f;
            #pragma unroll
            for (int w=0;w<8;w++) s += wred[w][e];
            lg[e] = s;
        }
        int i0=0; float v0=lg[0];
        #pragma unroll
        for (int e=1;e<Edim;e++) if (lg[e] > v0) { v0=lg[e]; i0=e; }
        int i1=-1; float v1=-3.4e38f;
        #pragma unroll
        for (int e=0;e<Edim;e++) if (e!=i0 && lg[e] > v1) { v1=lg[e]; i1=e; }
        const float ex  = __expf(v1 - v0);
        const float inv = 1.f/(1.f+ex);
        #pragma unroll
        for (int e=0;e<Edim;e++) gates[b*Edim+e] = 0.f;
        gates[b*Edim+i0] = inv;
        gates[b*Edim+i1] = ex*inv;
    }
}

__device__ __forceinline__ float cv_squared8(const float* t) {
    float mean = 0.f;
    #pragma unroll
    for (int e=0;e<Edim;e++) mean += t[e];
    mean *= (1.f/Edim);
    float var = 0.f;
    #pragma unroll
    for (int e=0;e<Edim;e++) { const float d = t[e]-mean; var += d*d; }
    var *= (1.f/(Edim-1));
    return var / (mean*mean + 1e-10f);
}

__global__ void gate_loss_kernel(const float* __restrict__ gates, float* __restrict__ loss_out) {
    __shared__ float sg[Bdim][Edim];
    const int b = threadIdx.x;
    #pragma unroll
    for (int e=0;e<Edim;e++) sg[b][e] = gates[b*Edim+e];
    __syncthreads();
    if (b == 0 && loss_out != nullptr) {
        float imp[Edim], ldc[Edim];
        #pragma unroll
        for (int e=0;e<Edim;e++) { imp[e]=0.f; ldc[e]=0.f; }
        for (int bb=0;bb<Bdim;bb++)
            #pragma unroll
            for (int e=0;e<Edim;e++) {
                const float g = sg[bb][e];
                imp[e] += g;
                if (g > 0.f) ldc[e] += 1.f;
            }
        loss_out[0] = 0.01f * (cv_squared8(imp) + cv_squared8(ldc));
    }
}

// ---------------- fused weight conversion (4 contiguous ranges) ----------------
#define R0 (3*Ddim*Ddim/4)           // in_w -> inw           : 786432
#define R1 (R0 + Ddim*Ddim/4)        // out_w -> outw         : +262144
#define R2 (R1 + 4*Ddim*Ddim/4)      // cfc_w -> bigw[0:4096] : +1048576
#define R3 (R2 + Edim*Rdim*Ddim/4)   // down_w -> bigw[4096:] : +131072

__global__ void convert_all_kernel(const float4* __restrict__ in_w,
                                   const float4* __restrict__ out_w,
                                   const float4* __restrict__ cfc_w,
                                   const float4* __restrict__ down_w,
                                   __half2* __restrict__ inw,
                                   __half2* __restrict__ outw,
                                   __half2* __restrict__ bigw) {
    const int i = blockIdx.x*blockDim.x + threadIdx.x;
    const float4* src; __half2* dst; int j;
    if (i < R0)       { src = in_w;   dst = inw;                    j = i; }
    else if (i < R1)  { src = out_w;  dst = outw;                   j = i - R0; }
    else if (i < R2)  { src = cfc_w;  dst = bigw;                   j = i - R1; }
    else if (i < R3)  { src = down_w; dst = bigw + 2*4*Ddim*Ddim/4; j = i - R2; }
    else return;
    const float4 v = src[j];
    dst[2*j+0] = __floats2half2_rn(v.x, v.y);
    dst[2*j+1] = __floats2half2_rn(v.z, v.w);
}

__global__ void f2h_cprw_kernel(const float* __restrict__ in, __half* __restrict__ out, int n4) {
    const int i = blockIdx.x*blockDim.x + threadIdx.x;
    if (i < n4) {
        const int n = i / (4*Ddim/4);
        const int c4 = i % (4*Ddim/4);
        const float4 v = ((const float4*)(in + (size_t)n*4*Ddim))[c4];
        __half2* dst = (__half2*)(out + (size_t)n*KEXT + c4*4);
        dst[0] = __floats2half2_rn(v.x, v.y);
        dst[1] = __floats2half2_rn(v.z, v.w);
    }
}
__global__ void transpose_up_kernel(const float* __restrict__ up_w, __half* __restrict__ out) {
    const int idx = blockIdx.x*blockDim.x + threadIdx.x;
    const int total = Ddim*Edim*Rdim/4;
    if (idx < total) {
        const int r4 = idx % (Rdim/4);
        const int de = idx / (Rdim/4);
        const int e = de % Edim;
        const int d = de / Edim;
        const float4 v = ((const float4*)(up_w + (size_t)e*Ddim*Rdim + (size_t)d*Rdim))[r4];
        __half2* dst = (__half2*)(out + (size_t)d*KEXT + 4*Ddim + e*Rdim + r4*4);
        dst[0] = __floats2half2_rn(SCALE_ADAPTER*v.x, SCALE_ADAPTER*v.y);
        dst[1] = __floats2half2_rn(SCALE_ADAPTER*v.z, SCALE_ADAPTER*v.w);
    }
}

// ---------------- launch ----------------
extern "C" void kernel_launch(void* const* d_in, const int* in_sizes, int n_in,
                              void* d_out, int out_size) {
    (void)in_sizes; (void)n_in;
    const float* x       = (const float*)d_in[0];
    const float* ln1_w   = (const float*)d_in[1];
    const float* ln1_b   = (const float*)d_in[2];
    const float* in_w    = (const float*)d_in[3];
    const float* in_b    = (const float*)d_in[4];
    const float* out_w   = (const float*)d_in[5];
    const float* out_b   = (const float*)d_in[6];
    const float* ln2_w   = (const float*)d_in[7];
    const float* ln2_b   = (const float*)d_in[8];
    const float* cfc_w   = (const float*)d_in[9];
    const float* cfc_b   = (const float*)d_in[10];
    const float* cproj_w = (const float*)d_in[11];
    const float* cproj_b = (const float*)d_in[12];
    const float* w_gate  = (const float*)d_in[13];
    const float* down_w  = (const float*)d_in[14];
    const float* down_b  = (const float*)d_in[15];
    const float* up_w    = (const float*)d_in[16];
    const float* up_b    = (const float*)d_in[17];
    float* out = (float*)d_out;

    void* p;
    cudaGetSymbolAddress(&p, g_lnx);   __half* lnx  = (__half*)p;
    cudaGetSymbolAddress(&p, g_qkv);   __half* qkv  = (__half*)p;
    cudaGetSymbolAddress(&p, g_attn);  __half* attn = (__half*)p;
    cudaGetSymbolAddress(&p, g_x1);    float*  x1   = (float*)p;
    cudaGetSymbolAddress(&p, g_x1h);   __half* x1h  = (__half*)p;
    cudaGetSymbolAddress(&p, g_ln2x);  __half* ln2x = (__half*)p;
    cudaGetSymbolAddress(&p, g_h2e);   __half* h2e  = (__half*)p;
    cudaGetSymbolAddress(&p, g_inw);   __half* inw  = (__half*)p;
    cudaGetSymbolAddress(&p, g_outw);  __half* outw = (__half*)p;
    cudaGetSymbolAddress(&p, g_bigw);  __half* bigw = (__half*)p;
    cudaGetSymbolAddress(&p, g_cprw2); __half* cprw2= (__half*)p;
    cudaGetSymbolAddress(&p, g_gates); float*  gates= (float*)p;

    cudaFuncSetAttribute(attn_mma_kernel, cudaFuncAttributeMaxDynamicSharedMemorySize, ATT_SMEM);
    cudaFuncSetAttribute((tgemm<__half, EpiBias>),      cudaFuncAttributeMaxDynamicSharedMemorySize, TGM_SMEM);
    cudaFuncSetAttribute((tgemm<float,  EpiOutProj>),   cudaFuncAttributeMaxDynamicSharedMemorySize, TGM_SMEM);
    cudaFuncSetAttribute((tgemm<__half, EpiGeluAdapt>), cudaFuncAttributeMaxDynamicSharedMemorySize, TGM_SMEM);
    cudaFuncSetAttribute((tgemm<float,  EpiFinal2>),    cudaFuncAttributeMaxDynamicSharedMemorySize, TGM_SMEM);

    float* loss_ptr = (out_size > NTOK*Ddim) ? (out + NTOK*Ddim) : nullptr;

    // 0) weight conversion fp32 -> fp16 (fused)
    convert_all_kernel<<<(R3+255)/256, 256>>>(
        (const float4*)in_w, (const float4*)out_w, (const float4*)cfc_w, (const float4*)down_w,
        (__half2*)inw, (__half2*)outw, (__half2*)bigw);
    f2h_cprw_kernel<<<(Ddim*Ddim+255)/256, 256>>>(cproj_w, cprw2, Ddim*Ddim);
    transpose_up_kernel<<<(Ddim*Edim*Rdim/4 + 255)/256, 256>>>(up_w, cprw2);

    // 1) LN1 (half)
    ln_kernel<<<NTOK, 256>>>(x, ln1_w, ln1_b, lnx);
    // 2) QKV projection (+bias) -> half
    tgemm<<<dim3(3*Ddim/128, NTOK/128), 256, TGM_SMEM>>>(lnx, lnx, 1<<30, inw, qkv,
        NTOK, 3*Ddim, Ddim, 3*Ddim, EpiBias{in_b});
    // 3) attention (tensor-core flash, no-max softmax) -> half
    attn_mma_kernel<<<Bdim*Hdim, 256, ATT_SMEM>>>(qkv, attn);
    // 4) out-proj (+bias, +x residual) -> x1 (fp32) and x1h (half)
    tgemm<<<dim3(Ddim/128, NTOK/128), 256, TGM_SMEM>>>(attn, attn, 1<<30, outw, x1,
        NTOK, Ddim, Ddim, Ddim, EpiOutProj{out_b, x, x1h});
    // 5) gating (parallel) + moe_loss
    gate_logits_kernel<<<Bdim, 256>>>(x1, w_gate, gates);
    gate_loss_kernel<<<1, Bdim>>>(gates, loss_ptr);
    // 6) LN2 (half)
    ln_kernel<<<NTOK, 256>>>(x1, ln2_w, ln2_b, ln2x);
    // 7+8) merged c_fc (A=ln2x, n<4096) + adapter down (A=x1h, n>=4096) -> h2e
    tgemm<<<dim3(KEXT/128, NTOK/128), 256, TGM_SMEM>>>(ln2x, x1h, 4*Ddim/128, bigw, h2e,
        NTOK, KEXT, Ddim, KEXT, EpiGeluAdapt{cfc_b, down_b, gates});
    // 9) merged c_proj + adapter up
    tgemm<<<dim3(Ddim/128, NTOK/128), 256, TGM_SMEM>>>(h2e, h2e, 1<<30, cprw2, out,
        NTOK, Ddim, KEXT, Ddim, EpiFinal2{cproj_b, x1, gates, up_b});
}